// round 2
// baseline (speedup 1.0000x reference)
#include <cuda_runtime.h>
#include <cstdint>

// ---------------------------------------------------------------------------
// SpinConvSq2dSparse: N=8, Lx=Ly=128, C=16, K=9 (-> 5 effective taps), F_IN=64
// Per-pixel GEMM I[4*64px, 48cols] = V @ W (K=80), thread tile 4x12, all
// shared-memory traffic via LDS.128 (feat tile de-interleaved at load).
// ---------------------------------------------------------------------------

#define TPAD 68      // feat tile row pad (floats) — 16B-aligned rows, bank-spread
#define NTP  194     // tile pixels: 66 (center+y halo) + 64 (x-1) + 64 (x+1)
#define WPAD 52      // weight row pad (floats)
#define IPAD 52      // intermediate row pad (floats)
#define TILE_FLOATS 13312                       // max(194*68=13192, 256*52=13312)
#define SMEM_FLOATS (2 * 80 * WPAD + TILE_FLOATS)   // 8320 + 13312 = 21632
#define SMEM_BYTES  (SMEM_FLOATS * 4)               // 86528 B

__device__ float g_WA[80 * WPAD];
__device__ float g_WB[80 * WPAD];

// ---------------------------------------------------------------------------
// Prep: build effective 5-tap weights with all scalar prefactors folded in.
// tap0 = sum of k=0..4 (all center); tap1..4 = k=5..8 -> (x-1),(x+1),(y-1),(y+1)
// cols: [0:16)=s110/a0-class, [16:32)=s101/b-class, [32:48)=t-class
// ---------------------------------------------------------------------------
__global__ void prep_weights(const float* __restrict__ w000,
                             const float* __restrict__ w011,
                             const float* __restrict__ w101,
                             const float* __restrict__ w110,
                             const float* __restrict__ w111) {
    int idx = blockIdx.x * blockDim.x + threadIdx.x;
    if (idx >= 80 * 48) return;
    int r   = idx / 48;        // (tap, c)
    int col = idx % 48;
    int tap = r / 16;
    int c   = r % 16;
    int cls = col / 16;
    int d   = col % 16;

    const double C0  = 0.28209479177387814;
    const double C1  = 0.4886025119029199;
    const double IS3 = 0.57735026918962576;   // 1/sqrt(3)
    const double IS6 = 0.40824829046386302;   // 1/sqrt(6)
    const double PW0 = 0.058925565098878960;  // sqrt(1/(9*2*16))
    const double PW1 = 1.0 / 12.0;            // sqrt(3/(9*3*16))

    int off = c * 16 + d;
    float s000, s011, s101, s110, s111;
    if (tap == 0) {
        s000 = s011 = s101 = s110 = s111 = 0.f;
        #pragma unroll
        for (int k = 0; k < 5; k++) {
            s000 += w000[k * 256 + off];
            s011 += w011[k * 256 + off];
            s101 += w101[k * 256 + off];
            s110 += w110[k * 256 + off];
            s111 += w111[k * 256 + off];
        }
    } else {
        int k = tap + 4;
        s000 = w000[k * 256 + off];
        s011 = w011[k * 256 + off];
        s101 = w101[k * 256 + off];
        s110 = w110[k * 256 + off];
        s111 = w111[k * 256 + off];
    }

    float a, b;
    if (cls == 0)      { a = (float)(PW0 * IS3 * C1) * s110;  b = (float)(PW0 * C0)       * s000; }
    else if (cls == 1) { a = (float)(PW1 * C0 * IS3) * s101;  b = (float)(PW1 * IS3 * C1) * s011; }
    else               { a = (float)(PW1 * IS6 * C1) * s111;  b = 0.f; }
    g_WA[r * WPAD + col] = a;
    g_WB[r * WPAD + col] = b;
}

// ---------------------------------------------------------------------------
// Main kernel: one CTA per (n, x, y-half of 64 pixels). 256 threads.
// GEMM: 256 rows (4 g-groups x 64 px) x 48 cols, K=80. Thread tile 4x12.
// ---------------------------------------------------------------------------
__global__ __launch_bounds__(256, 2)
void spinconv_kernel(const float* __restrict__ feat,
                     const float* __restrict__ spin,
                     float* __restrict__ out) {
    extern __shared__ float smem[];
    float* sWA = smem;
    float* sWB = smem + 80 * WPAD;
    float* sT  = smem + 2 * 80 * WPAD;   // feat tile, later reused for intermediates

    const int b   = blockIdx.x;
    const int n   = b >> 8;
    const int x   = (b >> 1) & 127;
    const int y0  = (b & 1) << 6;
    const int tid = threadIdx.x;

    // ---- load weights into smem (vectorized) ----
    #pragma unroll
    for (int i = tid; i < (80 * WPAD) / 4; i += 256) {
        ((float4*)sWA)[i] = ((const float4*)g_WA)[i];
        ((float4*)sWB)[i] = ((const float4*)g_WB)[i];
    }

    // ---- load feat tile (194 px x 64 floats), de-interleave to planes:
    //      [x0(16) | x1_i0(16) | x1_i1(16) | x1_i2(16)] per pixel row ----
    const int xm = (x + 127) & 127;
    const int xp = (x + 1) & 127;
    const size_t nbase = (size_t)n * (128 * 128 * 64);
    for (int idx = tid; idx < NTP * 16; idx += 256) {
        int tp = idx >> 4;
        int f4 = (idx & 15) << 2;
        int row, yy;
        if (tp < 66)       { row = x;  yy = (y0 + tp + 127) & 127; } // center row + y halo
        else if (tp < 130) { row = xm; yy = y0 + (tp - 66); }        // x-1
        else               { row = xp; yy = y0 + (tp - 130); }       // x+1
        float4 v = *(const float4*)(feat + nbase + ((size_t)row * 128 + yy) * 64 + f4);
        float vv[4] = {v.x, v.y, v.z, v.w};
        float* dst = sT + tp * TPAD;
        #pragma unroll
        for (int t = 0; t < 4; t++) {
            int f = f4 + t;
            int dpos;
            if (f < 16) dpos = f;
            else { int u = f - 16; dpos = (1 + (u % 3)) * 16 + (u / 3); }
            dst[dpos] = vv[t];
        }
    }
    __syncthreads();

    // ---- GEMM ----
    const int colg = tid & 3;           // 4 column groups of 12
    const int rowg = tid >> 2;          // 64 row groups of 4
    const int g    = rowg >> 4;         // 0..3 (warp-uniform)
    const int p0   = (rowg & 15) << 2;  // pixel base (4 consecutive pixels)
    const int j0   = colg * 12;
    const float* W     = (g == 3) ? sWB : sWA;
    const int    fbase = (g == 3) ? 0 : ((1 + g) << 4);   // plane start

    float acc[4][12];
    #pragma unroll
    for (int m = 0; m < 4; m++)
        #pragma unroll
        for (int j = 0; j < 12; j++) acc[m][j] = 0.f;

    #pragma unroll
    for (int tap = 0; tap < 5; tap++) {
        // tile pixel index of tap for pixel p: center=1+p, x-1=66+p, x+1=130+p, y-1=p, y+1=2+p
        const int base = (tap == 0) ? 1 : (tap == 1) ? 66 : (tap == 2) ? 130 : (tap == 3) ? 0 : 2;
        const float* tb = sT + (base + p0) * TPAD + fbase;
        const float* wr = W + tap * (16 * WPAD) + j0;
        #pragma unroll
        for (int c4 = 0; c4 < 4; c4++) {
            float xi[4][4];
            #pragma unroll
            for (int m = 0; m < 4; m++) {
                float4 v = *(const float4*)(tb + m * TPAD);
                xi[m][0] = v.x; xi[m][1] = v.y; xi[m][2] = v.z; xi[m][3] = v.w;
            }
            tb += 4;
            #pragma unroll
            for (int cc = 0; cc < 4; cc++) {
                float w[12];
                float4 wa = *(const float4*)(wr);
                float4 wb = *(const float4*)(wr + 4);
                float4 wc = *(const float4*)(wr + 8);
                w[0] = wa.x; w[1]  = wa.y; w[2]  = wa.z; w[3]  = wa.w;
                w[4] = wb.x; w[5]  = wb.y; w[6]  = wb.z; w[7]  = wb.w;
                w[8] = wc.x; w[9]  = wc.y; w[10] = wc.z; w[11] = wc.w;
                wr += WPAD;
                #pragma unroll
                for (int m = 0; m < 4; m++)
                    #pragma unroll
                    for (int j = 0; j < 12; j++)
                        acc[m][j] = fmaf(xi[m][cc], w[j], acc[m][j]);
            }
        }
    }
    __syncthreads();   // tile no longer needed; reuse sT for intermediates

    // ---- stash intermediates I[row=g*64+p][48] (pad IPAD) ----
    #pragma unroll
    for (int m = 0; m < 4; m++) {
        float* dst = sT + ((g << 6) + p0 + m) * IPAD + j0;
        *(float4*)(dst + 0) = make_float4(acc[m][0], acc[m][1], acc[m][2],  acc[m][3]);
        *(float4*)(dst + 4) = make_float4(acc[m][4], acc[m][5], acc[m][6],  acc[m][7]);
        *(float4*)(dst + 8) = make_float4(acc[m][8], acc[m][9], acc[m][10], acc[m][11]);
    }
    __syncthreads();

    // ---- epilogue: 4 threads per pixel, each does 4 d's ----
    const int p  = tid >> 2;
    const int d0 = (tid & 3) << 2;
    const size_t q = ((size_t)n * 128 + x) * 128 + (y0 + p);
    const float s0 = spin[q * 3 + 1];
    const float s1 = spin[q * 3 + 2];
    const float s2 = spin[q * 3 + 0];

    const float* I0 = sT + (0 * 64 + p) * IPAD;    // i=0 block
    const float* I1 = sT + (1 * 64 + p) * IPAD;    // i=1
    const float* I2 = sT + (2 * 64 + p) * IPAD;    // i=2
    const float* I3 = sT + (3 * 64 + p) * IPAD;    // x0 block: [a0|b|-]

    float o0[4], o1[12];
    #pragma unroll
    for (int t = 0; t < 4; t++) {
        const int d = d0 + t;
        const float a0 = I3[d];
        const float bv = I3[16 + d];
        const float h0 = I0[d],      h1 = I1[d],      h2 = I2[d];       // s110
        const float a1 = I0[16 + d], b1 = I1[16 + d], c1 = I2[16 + d];  // s101
        const float t0 = I0[32 + d], t1 = I1[32 + d], t2 = I2[32 + d];  // t

        o0[t] = a0 + h0 * s0 + h1 * s1 + h2 * s2;
        const float cx = t1 * s2 - t2 * s1;
        const float cy = t2 * s0 - t0 * s2;
        const float cz = t0 * s1 - t1 * s0;
        o1[t * 3 + 0] = fmaf(bv, s0, a1) + cx;
        o1[t * 3 + 1] = fmaf(bv, s1, b1) + cy;
        o1[t * 3 + 2] = fmaf(bv, s2, c1) + cz;
    }

    float* op = out + q * 64;
    *(float4*)(op + d0) = make_float4(o0[0], o0[1], o0[2], o0[3]);
    const int ob = 16 + 3 * d0;
    *(float4*)(op + ob + 0) = make_float4(o1[0], o1[1], o1[2],  o1[3]);
    *(float4*)(op + ob + 4) = make_float4(o1[4], o1[5], o1[6],  o1[7]);
    *(float4*)(op + ob + 8) = make_float4(o1[8], o1[9], o1[10], o1[11]);
}

// ---------------------------------------------------------------------------
extern "C" void kernel_launch(void* const* d_in, const int* in_sizes, int n_in,
                              void* d_out, int out_size) {
    const float* feat = (const float*)d_in[0];
    const float* spin = (const float*)d_in[1];
    const float* w000 = (const float*)d_in[2];
    const float* w011 = (const float*)d_in[3];
    const float* w101 = (const float*)d_in[4];
    const float* w110 = (const float*)d_in[5];
    const float* w111 = (const float*)d_in[6];
    float* out = (float*)d_out;

    (void)in_sizes; (void)n_in; (void)out_size;

    cudaFuncSetAttribute(spinconv_kernel,
                         cudaFuncAttributeMaxDynamicSharedMemorySize, SMEM_BYTES);

    prep_weights<<<(80 * 48 + 255) / 256, 256>>>(w000, w011, w101, w110, w111);
    spinconv_kernel<<<8 * 128 * 2, 256, SMEM_BYTES>>>(feat, spin, out);
}

// round 3
// speedup vs baseline: 1.1877x; 1.1877x over previous
#include <cuda_runtime.h>
#include <cstdint>

// ---------------------------------------------------------------------------
// SpinConvSq2dSparse: N=8, Lx=Ly=128, C=16, K=9 (-> 5 effective taps), F_IN=64
// Per-pixel GEMM I[4*64px, 48cols] = V @ W (K=80).
// Round 3: packed fp32 math via PTX fma.rn.f32x2 (Blackwell FFMA2).
//   - column-pairs packed in b64 accumulators (acc[4px][6pairs])
//   - weights load pre-packed (adjacent cols) as ulonglong2 from smem
//   - features duplicated into {x,x} via mov.b64 (1 mov per pixel per k)
// ---------------------------------------------------------------------------

#define TPAD 68      // feat tile row pad (floats) — 16B-aligned rows, bank-spread
#define NTP  194     // tile pixels: 66 (center+y halo) + 64 (x-1) + 64 (x+1)
#define WPAD 52      // weight row pad (floats)
#define IPAD 52      // intermediate row pad (floats)
#define TILE_FLOATS 13312                       // max(194*68=13192, 256*52=13312)
#define SMEM_FLOATS (2 * 80 * WPAD + TILE_FLOATS)   // 8320 + 13312 = 21632
#define SMEM_BYTES  (SMEM_FLOATS * 4)               // 86528 B

__device__ float g_WA[80 * WPAD];
__device__ float g_WB[80 * WPAD];

// ---- f32x2 helpers (sm_100a) ----
__device__ __forceinline__ unsigned long long f2dup(float x) {
    unsigned long long r;
    asm("mov.b64 %0, {%1, %1};" : "=l"(r) : "f"(x));
    return r;
}
__device__ __forceinline__ void fma2(unsigned long long& d,
                                     unsigned long long a,
                                     unsigned long long b) {
    asm("fma.rn.f32x2 %0, %1, %2, %0;" : "+l"(d) : "l"(a), "l"(b));
}
__device__ __forceinline__ void unpack2(unsigned long long v, float& lo, float& hi) {
    asm("mov.b64 {%0, %1}, %2;" : "=f"(lo), "=f"(hi) : "l"(v));
}

// ---------------------------------------------------------------------------
// Prep: build effective 5-tap weights with all scalar prefactors folded in.
// tap0 = sum of k=0..4 (all center); tap1..4 = k=5..8 -> (x-1),(x+1),(y-1),(y+1)
// cols: [0:16)=s110/a0-class, [16:32)=s101/b-class, [32:48)=t-class
// ---------------------------------------------------------------------------
__global__ void prep_weights(const float* __restrict__ w000,
                             const float* __restrict__ w011,
                             const float* __restrict__ w101,
                             const float* __restrict__ w110,
                             const float* __restrict__ w111) {
    int idx = blockIdx.x * blockDim.x + threadIdx.x;
    if (idx >= 80 * 48) return;
    int r   = idx / 48;        // (tap, c)
    int col = idx % 48;
    int tap = r / 16;
    int c   = r % 16;
    int cls = col / 16;
    int d   = col % 16;

    const double C0  = 0.28209479177387814;
    const double C1  = 0.4886025119029199;
    const double IS3 = 0.57735026918962576;   // 1/sqrt(3)
    const double IS6 = 0.40824829046386302;   // 1/sqrt(6)
    const double PW0 = 0.058925565098878960;  // sqrt(1/(9*2*16))
    const double PW1 = 1.0 / 12.0;            // sqrt(3/(9*3*16))

    int off = c * 16 + d;
    float s000, s011, s101, s110, s111;
    if (tap == 0) {
        s000 = s011 = s101 = s110 = s111 = 0.f;
        #pragma unroll
        for (int k = 0; k < 5; k++) {
            s000 += w000[k * 256 + off];
            s011 += w011[k * 256 + off];
            s101 += w101[k * 256 + off];
            s110 += w110[k * 256 + off];
            s111 += w111[k * 256 + off];
        }
    } else {
        int k = tap + 4;
        s000 = w000[k * 256 + off];
        s011 = w011[k * 256 + off];
        s101 = w101[k * 256 + off];
        s110 = w110[k * 256 + off];
        s111 = w111[k * 256 + off];
    }

    float a, b;
    if (cls == 0)      { a = (float)(PW0 * IS3 * C1) * s110;  b = (float)(PW0 * C0)       * s000; }
    else if (cls == 1) { a = (float)(PW1 * C0 * IS3) * s101;  b = (float)(PW1 * IS3 * C1) * s011; }
    else               { a = (float)(PW1 * IS6 * C1) * s111;  b = 0.f; }
    g_WA[r * WPAD + col] = a;
    g_WB[r * WPAD + col] = b;
}

// ---------------------------------------------------------------------------
// Main kernel: one CTA per (n, x, y-half of 64 pixels). 256 threads.
// GEMM: 256 rows (4 g-groups x 64 px) x 48 cols, K=80. Thread tile 4x12,
// columns processed as 6 packed pairs.
// ---------------------------------------------------------------------------
__global__ __launch_bounds__(256, 2)
void spinconv_kernel(const float* __restrict__ feat,
                     const float* __restrict__ spin,
                     float* __restrict__ out) {
    extern __shared__ float smem[];
    float* sWA = smem;
    float* sWB = smem + 80 * WPAD;
    float* sT  = smem + 2 * 80 * WPAD;   // feat tile, later reused for intermediates

    const int b   = blockIdx.x;
    const int n   = b >> 8;
    const int x   = (b >> 1) & 127;
    const int y0  = (b & 1) << 6;
    const int tid = threadIdx.x;

    // ---- load weights into smem (vectorized) ----
    #pragma unroll
    for (int i = tid; i < (80 * WPAD) / 4; i += 256) {
        ((float4*)sWA)[i] = ((const float4*)g_WA)[i];
        ((float4*)sWB)[i] = ((const float4*)g_WB)[i];
    }

    // ---- load feat tile (194 px x 64 floats), de-interleave to planes:
    //      [x0(16) | x1_i0(16) | x1_i1(16) | x1_i2(16)] per pixel row ----
    const int xm = (x + 127) & 127;
    const int xp = (x + 1) & 127;
    const size_t nbase = (size_t)n * (128 * 128 * 64);
    for (int idx = tid; idx < NTP * 16; idx += 256) {
        int tp = idx >> 4;
        int f4 = (idx & 15) << 2;
        int row, yy;
        if (tp < 66)       { row = x;  yy = (y0 + tp + 127) & 127; } // center row + y halo
        else if (tp < 130) { row = xm; yy = y0 + (tp - 66); }        // x-1
        else               { row = xp; yy = y0 + (tp - 130); }       // x+1
        float4 v = *(const float4*)(feat + nbase + ((size_t)row * 128 + yy) * 64 + f4);
        float vv[4] = {v.x, v.y, v.z, v.w};
        float* dst = sT + tp * TPAD;
        #pragma unroll
        for (int t = 0; t < 4; t++) {
            int f = f4 + t;
            int dpos;
            if (f < 16) dpos = f;
            else { int u = f - 16; dpos = (1 + (u % 3)) * 16 + (u / 3); }
            dst[dpos] = vv[t];
        }
    }
    __syncthreads();

    // ---- GEMM ----
    const int colg = tid & 3;           // 4 column groups of 12 (= 6 pairs)
    const int rowg = tid >> 2;          // 64 row groups of 4 pixels
    const int g    = rowg >> 4;         // 0..3 (warp-uniform)
    const int p0   = (rowg & 15) << 2;  // pixel base (4 consecutive pixels)
    const int j0   = colg * 12;
    const float* W     = (g == 3) ? sWB : sWA;
    const int    fbase = (g == 3) ? 0 : ((1 + g) << 4);   // plane start

    unsigned long long acc[4][6];
    #pragma unroll
    for (int m = 0; m < 4; m++)
        #pragma unroll
        for (int j = 0; j < 6; j++) acc[m][j] = 0ULL;

    #pragma unroll
    for (int tap = 0; tap < 5; tap++) {
        // tile pixel index of tap for pixel p: center=1+p, x-1=66+p, x+1=130+p, y-1=p, y+1=2+p
        const int base = (tap == 0) ? 1 : (tap == 1) ? 66 : (tap == 2) ? 130 : (tap == 3) ? 0 : 2;
        const float* tb = sT + (base + p0) * TPAD + fbase;
        const float* wr = W + tap * (16 * WPAD) + j0;
        #pragma unroll
        for (int c4 = 0; c4 < 4; c4++) {
            float4 v0 = *(const float4*)(tb + 0 * TPAD);
            float4 v1 = *(const float4*)(tb + 1 * TPAD);
            float4 v2 = *(const float4*)(tb + 2 * TPAD);
            float4 v3 = *(const float4*)(tb + 3 * TPAD);
            tb += 4;
            const float xs[4][4] = {{v0.x, v0.y, v0.z, v0.w},
                                    {v1.x, v1.y, v1.z, v1.w},
                                    {v2.x, v2.y, v2.z, v2.w},
                                    {v3.x, v3.y, v3.z, v3.w}};
            #pragma unroll
            for (int cc = 0; cc < 4; cc++) {
                // 6 packed column-pair weights (contiguous, 16B aligned)
                ulonglong2 wv0 = *(const ulonglong2*)(wr);
                ulonglong2 wv1 = *(const ulonglong2*)(wr + 4);
                ulonglong2 wv2 = *(const ulonglong2*)(wr + 8);
                wr += WPAD;
                unsigned long long xd0 = f2dup(xs[0][cc]);
                unsigned long long xd1 = f2dup(xs[1][cc]);
                unsigned long long xd2 = f2dup(xs[2][cc]);
                unsigned long long xd3 = f2dup(xs[3][cc]);
                fma2(acc[0][0], xd0, wv0.x); fma2(acc[0][1], xd0, wv0.y);
                fma2(acc[0][2], xd0, wv1.x); fma2(acc[0][3], xd0, wv1.y);
                fma2(acc[0][4], xd0, wv2.x); fma2(acc[0][5], xd0, wv2.y);
                fma2(acc[1][0], xd1, wv0.x); fma2(acc[1][1], xd1, wv0.y);
                fma2(acc[1][2], xd1, wv1.x); fma2(acc[1][3], xd1, wv1.y);
                fma2(acc[1][4], xd1, wv2.x); fma2(acc[1][5], xd1, wv2.y);
                fma2(acc[2][0], xd2, wv0.x); fma2(acc[2][1], xd2, wv0.y);
                fma2(acc[2][2], xd2, wv1.x); fma2(acc[2][3], xd2, wv1.y);
                fma2(acc[2][4], xd2, wv2.x); fma2(acc[2][5], xd2, wv2.y);
                fma2(acc[3][0], xd3, wv0.x); fma2(acc[3][1], xd3, wv0.y);
                fma2(acc[3][2], xd3, wv1.x); fma2(acc[3][3], xd3, wv1.y);
                fma2(acc[3][4], xd3, wv2.x); fma2(acc[3][5], xd3, wv2.y);
            }
        }
    }
    __syncthreads();   // tile no longer needed; reuse sT for intermediates

    // ---- stash intermediates I[row=g*64+p][48] (pad IPAD) ----
    #pragma unroll
    for (int m = 0; m < 4; m++) {
        float o[12];
        #pragma unroll
        for (int j = 0; j < 6; j++) unpack2(acc[m][j], o[2 * j], o[2 * j + 1]);
        float* dst = sT + ((g << 6) + p0 + m) * IPAD + j0;
        *(float4*)(dst + 0) = make_float4(o[0], o[1], o[2],  o[3]);
        *(float4*)(dst + 4) = make_float4(o[4], o[5], o[6],  o[7]);
        *(float4*)(dst + 8) = make_float4(o[8], o[9], o[10], o[11]);
    }
    __syncthreads();

    // ---- epilogue: 4 threads per pixel, each does 4 d's ----
    const int p  = tid >> 2;
    const int d0 = (tid & 3) << 2;
    const size_t q = ((size_t)n * 128 + x) * 128 + (y0 + p);
    const float s0 = spin[q * 3 + 1];
    const float s1 = spin[q * 3 + 2];
    const float s2 = spin[q * 3 + 0];

    const float* I0 = sT + (0 * 64 + p) * IPAD;    // i=0 block
    const float* I1 = sT + (1 * 64 + p) * IPAD;    // i=1
    const float* I2 = sT + (2 * 64 + p) * IPAD;    // i=2
    const float* I3 = sT + (3 * 64 + p) * IPAD;    // x0 block: [a0|b|-]

    float o0[4], o1[12];
    #pragma unroll
    for (int t = 0; t < 4; t++) {
        const int d = d0 + t;
        const float a0 = I3[d];
        const float bv = I3[16 + d];
        const float h0 = I0[d],      h1 = I1[d],      h2 = I2[d];       // s110
        const float a1 = I0[16 + d], b1 = I1[16 + d], c1 = I2[16 + d];  // s101
        const float t0 = I0[32 + d], t1 = I1[32 + d], t2 = I2[32 + d];  // t

        o0[t] = a0 + h0 * s0 + h1 * s1 + h2 * s2;
        const float cx = t1 * s2 - t2 * s1;
        const float cy = t2 * s0 - t0 * s2;
        const float cz = t0 * s1 - t1 * s0;
        o1[t * 3 + 0] = fmaf(bv, s0, a1) + cx;
        o1[t * 3 + 1] = fmaf(bv, s1, b1) + cy;
        o1[t * 3 + 2] = fmaf(bv, s2, c1) + cz;
    }

    float* op = out + q * 64;
    *(float4*)(op + d0) = make_float4(o0[0], o0[1], o0[2], o0[3]);
    const int ob = 16 + 3 * d0;
    *(float4*)(op + ob + 0) = make_float4(o1[0], o1[1], o1[2],  o1[3]);
    *(float4*)(op + ob + 4) = make_float4(o1[4], o1[5], o1[6],  o1[7]);
    *(float4*)(op + ob + 8) = make_float4(o1[8], o1[9], o1[10], o1[11]);
}

// ---------------------------------------------------------------------------
extern "C" void kernel_launch(void* const* d_in, const int* in_sizes, int n_in,
                              void* d_out, int out_size) {
    const float* feat = (const float*)d_in[0];
    const float* spin = (const float*)d_in[1];
    const float* w000 = (const float*)d_in[2];
    const float* w011 = (const float*)d_in[3];
    const float* w101 = (const float*)d_in[4];
    const float* w110 = (const float*)d_in[5];
    const float* w111 = (const float*)d_in[6];
    float* out = (float*)d_out;

    (void)in_sizes; (void)n_in; (void)out_size;

    cudaFuncSetAttribute(spinconv_kernel,
                         cudaFuncAttributeMaxDynamicSharedMemorySize, SMEM_BYTES);

    prep_weights<<<(80 * 48 + 255) / 256, 256>>>(w000, w011, w101, w110, w111);
    spinconv_kernel<<<8 * 128 * 2, 256, SMEM_BYTES>>>(feat, spin, out);
}

// round 4
// speedup vs baseline: 1.2453x; 1.0485x over previous
#include <cuda_runtime.h>
#include <cstdint>

// ---------------------------------------------------------------------------
// SpinConvSq2dSparse: N=8, Lx=Ly=128, C=16, K=9 (-> 5 effective taps), F_IN=64
// Per-pixel GEMM I[4*64px, 48cols] = V @ W (K=80), fma.rn.f32x2 packed math.
// Round 4: interleaved pixel->thread mapping (p, p+16, p+32, p+48) so the
// 8 row-lanes of a warp stride by 1 pixel (68 words == 4 mod 32) -> all 32
// banks covered, conflict-free feat loads (was 4-way conflicted).
// ---------------------------------------------------------------------------

#define TPAD 68      // feat tile row pad (floats); 68 % 8 == 4 -> lane spread
#define NTP  194     // tile pixels: 66 (center+y halo) + 64 (x-1) + 64 (x+1)
#define WPAD 52      // weight row pad (floats)
#define IPAD 52      // intermediate row pad (floats); 52 % 32 == 20 -> spread
#define TILE_FLOATS 13312                       // max(194*68=13192, 256*52=13312)
#define SMEM_FLOATS (2 * 80 * WPAD + TILE_FLOATS)   // 8320 + 13312 = 21632
#define SMEM_BYTES  (SMEM_FLOATS * 4)               // 86528 B

__device__ float g_WA[80 * WPAD];
__device__ float g_WB[80 * WPAD];

// ---- f32x2 helpers (sm_100a) ----
__device__ __forceinline__ unsigned long long f2dup(float x) {
    unsigned long long r;
    asm("mov.b64 %0, {%1, %1};" : "=l"(r) : "f"(x));
    return r;
}
__device__ __forceinline__ void fma2(unsigned long long& d,
                                     unsigned long long a,
                                     unsigned long long b) {
    asm("fma.rn.f32x2 %0, %1, %2, %0;" : "+l"(d) : "l"(a), "l"(b));
}
__device__ __forceinline__ void unpack2(unsigned long long v, float& lo, float& hi) {
    asm("mov.b64 {%0, %1}, %2;" : "=f"(lo), "=f"(hi) : "l"(v));
}

// ---------------------------------------------------------------------------
// Prep: build effective 5-tap weights with all scalar prefactors folded in.
// tap0 = sum of k=0..4 (all center); tap1..4 = k=5..8 -> (x-1),(x+1),(y-1),(y+1)
// cols: [0:16)=s110/a0-class, [16:32)=s101/b-class, [32:48)=t-class
// ---------------------------------------------------------------------------
__global__ void prep_weights(const float* __restrict__ w000,
                             const float* __restrict__ w011,
                             const float* __restrict__ w101,
                             const float* __restrict__ w110,
                             const float* __restrict__ w111) {
    int idx = blockIdx.x * blockDim.x + threadIdx.x;
    if (idx >= 80 * 48) return;
    int r   = idx / 48;        // (tap, c)
    int col = idx % 48;
    int tap = r / 16;
    int c   = r % 16;
    int cls = col / 16;
    int d   = col % 16;

    const double C0  = 0.28209479177387814;
    const double C1  = 0.4886025119029199;
    const double IS3 = 0.57735026918962576;   // 1/sqrt(3)
    const double IS6 = 0.40824829046386302;   // 1/sqrt(6)
    const double PW0 = 0.058925565098878960;  // sqrt(1/(9*2*16))
    const double PW1 = 1.0 / 12.0;            // sqrt(3/(9*3*16))

    int off = c * 16 + d;
    float s000, s011, s101, s110, s111;
    if (tap == 0) {
        s000 = s011 = s101 = s110 = s111 = 0.f;
        #pragma unroll
        for (int k = 0; k < 5; k++) {
            s000 += w000[k * 256 + off];
            s011 += w011[k * 256 + off];
            s101 += w101[k * 256 + off];
            s110 += w110[k * 256 + off];
            s111 += w111[k * 256 + off];
        }
    } else {
        int k = tap + 4;
        s000 = w000[k * 256 + off];
        s011 = w011[k * 256 + off];
        s101 = w101[k * 256 + off];
        s110 = w110[k * 256 + off];
        s111 = w111[k * 256 + off];
    }

    float a, b;
    if (cls == 0)      { a = (float)(PW0 * IS3 * C1) * s110;  b = (float)(PW0 * C0)       * s000; }
    else if (cls == 1) { a = (float)(PW1 * C0 * IS3) * s101;  b = (float)(PW1 * IS3 * C1) * s011; }
    else               { a = (float)(PW1 * IS6 * C1) * s111;  b = 0.f; }
    g_WA[r * WPAD + col] = a;
    g_WB[r * WPAD + col] = b;
}

// ---------------------------------------------------------------------------
// Main kernel: one CTA per (n, x, y-half of 64 pixels). 256 threads.
// GEMM: 256 rows (4 g-groups x 64 px) x 48 cols, K=80. Thread tile 4x12,
// columns as 6 packed pairs; pixels interleaved (p0 + 16*m).
// ---------------------------------------------------------------------------
__global__ __launch_bounds__(256, 2)
void spinconv_kernel(const float* __restrict__ feat,
                     const float* __restrict__ spin,
                     float* __restrict__ out) {
    extern __shared__ float smem[];
    float* sWA = smem;
    float* sWB = smem + 80 * WPAD;
    float* sT  = smem + 2 * 80 * WPAD;   // feat tile, later reused for intermediates

    const int b   = blockIdx.x;
    const int n   = b >> 8;
    const int x   = (b >> 1) & 127;
    const int y0  = (b & 1) << 6;
    const int tid = threadIdx.x;

    // ---- load weights into smem (vectorized) ----
    #pragma unroll
    for (int i = tid; i < (80 * WPAD) / 4; i += 256) {
        ((float4*)sWA)[i] = ((const float4*)g_WA)[i];
        ((float4*)sWB)[i] = ((const float4*)g_WB)[i];
    }

    // ---- load feat tile (194 px x 64 floats), de-interleave to planes:
    //      [x0(16) | x1_i0(16) | x1_i1(16) | x1_i2(16)] per pixel row ----
    const int xm = (x + 127) & 127;
    const int xp = (x + 1) & 127;
    const size_t nbase = (size_t)n * (128 * 128 * 64);
    for (int idx = tid; idx < NTP * 16; idx += 256) {
        int tp = idx >> 4;
        int f4 = (idx & 15) << 2;
        int row, yy;
        if (tp < 66)       { row = x;  yy = (y0 + tp + 127) & 127; } // center row + y halo
        else if (tp < 130) { row = xm; yy = y0 + (tp - 66); }        // x-1
        else               { row = xp; yy = y0 + (tp - 130); }       // x+1
        float4 v = *(const float4*)(feat + nbase + ((size_t)row * 128 + yy) * 64 + f4);
        float vv[4] = {v.x, v.y, v.z, v.w};
        float* dst = sT + tp * TPAD;
        #pragma unroll
        for (int t = 0; t < 4; t++) {
            int f = f4 + t;
            int dpos;
            if (f < 16) dpos = f;
            else { int u = f - 16; dpos = (1 + (u % 3)) * 16 + (u / 3); }
            dst[dpos] = vv[t];
        }
    }
    __syncthreads();

    // ---- GEMM ----
    const int colg = tid & 3;           // 4 column groups of 12 (= 6 pairs)
    const int rowg = tid >> 2;          // 64 row groups of 4 pixels
    const int g    = rowg >> 4;         // 0..3 (warp-uniform)
    const int p0   = rowg & 15;         // pixel base; thread does p0 + 16*m
    const int j0   = colg * 12;
    const float* W     = (g == 3) ? sWB : sWA;
    const int    fbase = (g == 3) ? 0 : ((1 + g) << 4);   // plane start

    unsigned long long acc[4][6];
    #pragma unroll
    for (int m = 0; m < 4; m++)
        #pragma unroll
        for (int j = 0; j < 6; j++) acc[m][j] = 0ULL;

    #pragma unroll
    for (int tap = 0; tap < 5; tap++) {
        // tile pixel index of tap for pixel p: center=1+p, x-1=66+p, x+1=130+p, y-1=p, y+1=2+p
        const int base = (tap == 0) ? 1 : (tap == 1) ? 66 : (tap == 2) ? 130 : (tap == 3) ? 0 : 2;
        const float* tb = sT + (base + p0) * TPAD + fbase;
        const float* wr = W + tap * (16 * WPAD) + j0;
        #pragma unroll
        for (int c4 = 0; c4 < 4; c4++) {
            float4 v0 = *(const float4*)(tb + 0 * 16 * TPAD);
            float4 v1 = *(const float4*)(tb + 1 * 16 * TPAD);
            float4 v2 = *(const float4*)(tb + 2 * 16 * TPAD);
            float4 v3 = *(const float4*)(tb + 3 * 16 * TPAD);
            tb += 4;
            const float xs[4][4] = {{v0.x, v0.y, v0.z, v0.w},
                                    {v1.x, v1.y, v1.z, v1.w},
                                    {v2.x, v2.y, v2.z, v2.w},
                                    {v3.x, v3.y, v3.z, v3.w}};
            #pragma unroll
            for (int cc = 0; cc < 4; cc++) {
                // 6 packed column-pair weights (contiguous, 16B aligned)
                ulonglong2 wv0 = *(const ulonglong2*)(wr);
                ulonglong2 wv1 = *(const ulonglong2*)(wr + 4);
                ulonglong2 wv2 = *(const ulonglong2*)(wr + 8);
                wr += WPAD;
                unsigned long long xd0 = f2dup(xs[0][cc]);
                unsigned long long xd1 = f2dup(xs[1][cc]);
                unsigned long long xd2 = f2dup(xs[2][cc]);
                unsigned long long xd3 = f2dup(xs[3][cc]);
                fma2(acc[0][0], xd0, wv0.x); fma2(acc[0][1], xd0, wv0.y);
                fma2(acc[0][2], xd0, wv1.x); fma2(acc[0][3], xd0, wv1.y);
                fma2(acc[0][4], xd0, wv2.x); fma2(acc[0][5], xd0, wv2.y);
                fma2(acc[1][0], xd1, wv0.x); fma2(acc[1][1], xd1, wv0.y);
                fma2(acc[1][2], xd1, wv1.x); fma2(acc[1][3], xd1, wv1.y);
                fma2(acc[1][4], xd1, wv2.x); fma2(acc[1][5], xd1, wv2.y);
                fma2(acc[2][0], xd2, wv0.x); fma2(acc[2][1], xd2, wv0.y);
                fma2(acc[2][2], xd2, wv1.x); fma2(acc[2][3], xd2, wv1.y);
                fma2(acc[2][4], xd2, wv2.x); fma2(acc[2][5], xd2, wv2.y);
                fma2(acc[3][0], xd3, wv0.x); fma2(acc[3][1], xd3, wv0.y);
                fma2(acc[3][2], xd3, wv1.x); fma2(acc[3][3], xd3, wv1.y);
                fma2(acc[3][4], xd3, wv2.x); fma2(acc[3][5], xd3, wv2.y);
            }
        }
    }
    __syncthreads();   // tile no longer needed; reuse sT for intermediates

    // ---- stash intermediates I[row=g*64+p][48] (pad IPAD) ----
    #pragma unroll
    for (int m = 0; m < 4; m++) {
        float o[12];
        #pragma unroll
        for (int j = 0; j < 6; j++) unpack2(acc[m][j], o[2 * j], o[2 * j + 1]);
        float* dst = sT + ((g << 6) + p0 + 16 * m) * IPAD + j0;
        *(float4*)(dst + 0) = make_float4(o[0], o[1], o[2],  o[3]);
        *(float4*)(dst + 4) = make_float4(o[4], o[5], o[6],  o[7]);
        *(float4*)(dst + 8) = make_float4(o[8], o[9], o[10], o[11]);
    }
    __syncthreads();

    // ---- epilogue: 4 threads per pixel, each does 4 d's ----
    const int p  = tid >> 2;
    const int d0 = (tid & 3) << 2;
    const size_t q = ((size_t)n * 128 + x) * 128 + (y0 + p);
    const float s0 = spin[q * 3 + 1];
    const float s1 = spin[q * 3 + 2];
    const float s2 = spin[q * 3 + 0];

    const float* I0 = sT + (0 * 64 + p) * IPAD;    // i=0 block
    const float* I1 = sT + (1 * 64 + p) * IPAD;    // i=1
    const float* I2 = sT + (2 * 64 + p) * IPAD;    // i=2
    const float* I3 = sT + (3 * 64 + p) * IPAD;    // x0 block: [a0|b|-]

    float o0[4], o1[12];
    #pragma unroll
    for (int t = 0; t < 4; t++) {
        const int d = d0 + t;
        const float a0 = I3[d];
        const float bv = I3[16 + d];
        const float h0 = I0[d],      h1 = I1[d],      h2 = I2[d];       // s110
        const float a1 = I0[16 + d], b1 = I1[16 + d], c1 = I2[16 + d];  // s101
        const float t0 = I0[32 + d], t1 = I1[32 + d], t2 = I2[32 + d];  // t

        o0[t] = a0 + h0 * s0 + h1 * s1 + h2 * s2;
        const float cx = t1 * s2 - t2 * s1;
        const float cy = t2 * s0 - t0 * s2;
        const float cz = t0 * s1 - t1 * s0;
        o1[t * 3 + 0] = fmaf(bv, s0, a1) + cx;
        o1[t * 3 + 1] = fmaf(bv, s1, b1) + cy;
        o1[t * 3 + 2] = fmaf(bv, s2, c1) + cz;
    }

    float* op = out + q * 64;
    *(float4*)(op + d0) = make_float4(o0[0], o0[1], o0[2], o0[3]);
    const int ob = 16 + 3 * d0;
    *(float4*)(op + ob + 0) = make_float4(o1[0], o1[1], o1[2],  o1[3]);
    *(float4*)(op + ob + 4) = make_float4(o1[4], o1[5], o1[6],  o1[7]);
    *(float4*)(op + ob + 8) = make_float4(o1[8], o1[9], o1[10], o1[11]);
}

// ---------------------------------------------------------------------------
extern "C" void kernel_launch(void* const* d_in, const int* in_sizes, int n_in,
                              void* d_out, int out_size) {
    const float* feat = (const float*)d_in[0];
    const float* spin = (const float*)d_in[1];
    const float* w000 = (const float*)d_in[2];
    const float* w011 = (const float*)d_in[3];
    const float* w101 = (const float*)d_in[4];
    const float* w110 = (const float*)d_in[5];
    const float* w111 = (const float*)d_in[6];
    float* out = (float*)d_out;

    (void)in_sizes; (void)n_in; (void)out_size;

    cudaFuncSetAttribute(spinconv_kernel,
                         cudaFuncAttributeMaxDynamicSharedMemorySize, SMEM_BYTES);

    prep_weights<<<(80 * 48 + 255) / 256, 256>>>(w000, w011, w101, w110, w111);
    spinconv_kernel<<<8 * 128 * 2, 256, SMEM_BYTES>>>(feat, spin, out);
}